// round 1
// baseline (speedup 1.0000x reference)
#include <cuda_runtime.h>

#define B_SETS 256
#define S_LEN  1024
#define H_DIM  256
#define M_ROWS (B_SETS * S_LEN)

// Scratch (allocation-free rule: __device__ globals)
__device__ float g_bufA[(size_t)M_ROWS * H_DIM];   // 256 MB
__device__ float g_bufB[(size_t)M_ROWS * H_DIM];   // 256 MB
__device__ float g_mean[B_SETS * H_DIM];
__device__ float g_cbias[B_SETS * H_DIM];

// ---------------------------------------------------------------------------
// mean over the set dimension: in [B, S, d] -> out [B, d]  (out = sum/S)
// ---------------------------------------------------------------------------
__global__ void mean_kernel(const float* __restrict__ in, float* __restrict__ out, int d) {
    int b = blockIdx.x;
    int t = threadIdx.x;
    if (t >= d) return;
    const float* p = in + (size_t)b * S_LEN * d + t;
    float s = 0.f;
#pragma unroll 8
    for (int i = 0; i < S_LEN; i++) s += p[(size_t)i * d];
    out[b * d + t] = s * (1.0f / S_LEN);
}

// ---------------------------------------------------------------------------
// per-set bias: c[b,h] = bias[h] + sum_k mean[b,k] * W[h, koff + k]
// W row-major [H, ldw]
// ---------------------------------------------------------------------------
__global__ void cbias_kernel(const float* __restrict__ mean, const float* __restrict__ W,
                             const float* __restrict__ bias, float* __restrict__ c,
                             int K, int ldw, int koff) {
    __shared__ float ms[H_DIM];
    int b = blockIdx.x;
    int h = threadIdx.x;
    if (h < K) ms[h] = mean[b * K + h];
    __syncthreads();
    const float* wrow = W + (size_t)h * ldw + koff;
    float s = bias[h];
#pragma unroll 8
    for (int k = 0; k < K; k++) s += ms[k] * wrow[k];
    c[b * H_DIM + h] = s;
}

// ---------------------------------------------------------------------------
// Out[m, n] = tanh( sum_k A[m,k] * W[n,k]  +  C[set(m), n] )
// A: [M, K] row-major (K = ld of A). W: [H_DIM, ldw] row-major, using cols [0,K).
// C: [B_SETS, H_DIM]. Out: [M, H_DIM].
// Tile: 128x128x8, 256 threads, 8x8 per thread.
// ---------------------------------------------------------------------------
#define BM 128
#define BN 128
#define BK 8
#define TM 8
#define TN 8

__global__ __launch_bounds__(256) void gemm_tanh_kernel(
    const float* __restrict__ A, const float* __restrict__ W,
    const float* __restrict__ C, float* __restrict__ Out,
    int K, int ldw)
{
    __shared__ float As[BK][BM + 4];
    __shared__ float Bs[BK][BN + 4];

    const int tid = threadIdx.x;
    const int tx  = tid & 15;       // 0..15
    const int ty  = tid >> 4;       // 0..15
    const int m0  = blockIdx.x * BM;
    const int n0  = blockIdx.y * BN;
    const int bset = m0 >> 10;      // BM=128 divides S_LEN=1024 -> whole tile same set

    // loader mapping: each thread loads one float4 per tile from A and from W
    const int lm = tid >> 1;              // 0..127 (row within tile)
    const int lk = (tid & 1) * 4;         // 0 or 4 (k offset)
    const float* Aptr = A + (size_t)(m0 + lm) * K + lk;
    const float* Wptr = W + (size_t)(n0 + lm) * ldw + lk;

    float acc[TM][TN];
#pragma unroll
    for (int i = 0; i < TM; i++)
#pragma unroll
        for (int j = 0; j < TN; j++) acc[i][j] = 0.f;

    for (int k0 = 0; k0 < K; k0 += BK) {
        float4 av = *(const float4*)(Aptr + k0);
        float4 wv = *(const float4*)(Wptr + k0);
        As[lk + 0][lm] = av.x;
        As[lk + 1][lm] = av.y;
        As[lk + 2][lm] = av.z;
        As[lk + 3][lm] = av.w;
        Bs[lk + 0][lm] = wv.x;
        Bs[lk + 1][lm] = wv.y;
        Bs[lk + 2][lm] = wv.z;
        Bs[lk + 3][lm] = wv.w;
        __syncthreads();

#pragma unroll
        for (int kk = 0; kk < BK; kk++) {
            float a[TM], bb[TN];
#pragma unroll
            for (int i = 0; i < TM; i++) a[i] = As[kk][ty * TM + i];
#pragma unroll
            for (int j = 0; j < TN; j++) bb[j] = Bs[kk][tx * TN + j];
#pragma unroll
            for (int i = 0; i < TM; i++)
#pragma unroll
                for (int j = 0; j < TN; j++)
                    acc[i][j] += a[i] * bb[j];
        }
        __syncthreads();
    }

    // epilogue: add per-set bias, tanh, store (two float4 per row)
    const float* crow = C + bset * H_DIM + n0 + tx * TN;
#pragma unroll
    for (int i = 0; i < TM; i++) {
        int row = m0 + ty * TM + i;
        float* orow = Out + (size_t)row * H_DIM + n0 + tx * TN;
        float4 v0, v1;
        v0.x = tanhf(acc[i][0] + crow[0]);
        v0.y = tanhf(acc[i][1] + crow[1]);
        v0.z = tanhf(acc[i][2] + crow[2]);
        v0.w = tanhf(acc[i][3] + crow[3]);
        v1.x = tanhf(acc[i][4] + crow[4]);
        v1.y = tanhf(acc[i][5] + crow[5]);
        v1.z = tanhf(acc[i][6] + crow[6]);
        v1.w = tanhf(acc[i][7] + crow[7]);
        ((float4*)orow)[0] = v0;
        ((float4*)orow)[1] = v1;
    }
}

// ---------------------------------------------------------------------------
extern "C" void kernel_launch(void* const* d_in, const int* in_sizes, int n_in,
                              void* d_out, int out_size) {
    const float* x  = (const float*)d_in[0];
    const float* W0 = (const float*)d_in[1];
    const float* b0 = (const float*)d_in[2];
    const float* W1 = (const float*)d_in[3];
    const float* b1 = (const float*)d_in[4];
    const float* W2 = (const float*)d_in[5];
    const float* b2 = (const float*)d_in[6];
    float* out = (float*)d_out;

    float *bufA, *bufB, *mean, *cb;
    cudaGetSymbolAddress((void**)&bufA, g_bufA);
    cudaGetSymbolAddress((void**)&bufB, g_bufB);
    cudaGetSymbolAddress((void**)&mean, g_mean);
    cudaGetSymbolAddress((void**)&cb,   g_cbias);

    dim3 gg(M_ROWS / BM, H_DIM / BN);

    // Layer 0: K=128, W0 [256, 256] (Wy = cols [0,128), Wm = cols [128,256))
    mean_kernel<<<B_SETS, 128>>>(x, mean, 128);
    cbias_kernel<<<B_SETS, H_DIM>>>(mean, W0, b0, cb, 128, 256, 128);
    gemm_tanh_kernel<<<gg, 256>>>(x, W0, cb, bufA, 128, 256);

    // Layer 1: K=256, W1 [256, 512]
    mean_kernel<<<B_SETS, H_DIM>>>(bufA, mean, 256);
    cbias_kernel<<<B_SETS, H_DIM>>>(mean, W1, b1, cb, 256, 512, 256);
    gemm_tanh_kernel<<<gg, 256>>>(bufA, W1, cb, bufB, 256, 512);

    // Layer 2: K=256, W2 [256, 512]
    mean_kernel<<<B_SETS, H_DIM>>>(bufB, mean, 256);
    cbias_kernel<<<B_SETS, H_DIM>>>(mean, W2, b2, cb, 256, 512, 256);
    gemm_tanh_kernel<<<gg, 256>>>(bufB, W2, cb, bufA, 256, 512);

    // Final mean-pool -> output [B, 256]
    mean_kernel<<<B_SETS, H_DIM>>>(bufA, out, 256);
}

// round 4
// speedup vs baseline: 2.3223x; 2.3223x over previous
#include <cuda_runtime.h>
#include <cuda_bf16.h>
#include <cstdint>

#define B_SETS 256
#define S_LEN  1024
#define H_DIM  256
#define M_ROWS (B_SETS * S_LEN)

// ---------------------------------------------------------------------------
// Scratch (__device__ globals; allocation-free rule)
// ---------------------------------------------------------------------------
__device__ __nv_bfloat16 g_hi1[(size_t)M_ROWS * H_DIM];
__device__ __nv_bfloat16 g_lo1[(size_t)M_ROWS * H_DIM];
__device__ __nv_bfloat16 g_hi2[(size_t)M_ROWS * H_DIM];
__device__ __nv_bfloat16 g_lo2[(size_t)M_ROWS * H_DIM];
__device__ __nv_bfloat16 g_whi0[H_DIM * 128], g_wlo0[H_DIM * 128];
__device__ __nv_bfloat16 g_whi1[H_DIM * H_DIM], g_wlo1[H_DIM * H_DIM];
__device__ __nv_bfloat16 g_whi2[H_DIM * H_DIM], g_wlo2[H_DIM * H_DIM];
__device__ float g_msum[B_SETS * H_DIM];   // column sums (per set)
__device__ float g_cb[B_SETS * H_DIM];     // per-set bias c[b,h]

// ---------------------------------------------------------------------------
// helpers
// ---------------------------------------------------------------------------
__device__ __forceinline__ uint32_t smem_u32(const void* p) {
    uint32_t a;
    asm("{ .reg .u64 t; cvta.to.shared.u64 t, %1; cvt.u32.u64 %0, t; }" : "=r"(a) : "l"(p));
    return a;
}
#define SW128(o) ((o) ^ ((((uint32_t)(o)) >> 3) & 0x70u))

__device__ __forceinline__ void ldsm_x4(uint32_t* r, uint32_t addr) {
    asm volatile("ldmatrix.sync.aligned.m8n8.x4.shared.b16 {%0,%1,%2,%3}, [%4];"
                 : "=r"(r[0]), "=r"(r[1]), "=r"(r[2]), "=r"(r[3]) : "r"(addr));
}
__device__ __forceinline__ void mma_bf16(float* d, const uint32_t* a, uint32_t b0, uint32_t b1) {
    asm volatile(
        "mma.sync.aligned.m16n8k16.row.col.f32.bf16.bf16.f32 "
        "{%0,%1,%2,%3},{%4,%5,%6,%7},{%8,%9},{%0,%1,%2,%3};"
        : "+f"(d[0]), "+f"(d[1]), "+f"(d[2]), "+f"(d[3])
        : "r"(a[0]), "r"(a[1]), "r"(a[2]), "r"(a[3]), "r"(b0), "r"(b1));
}
__device__ __forceinline__ float tanh_fast(float x) {
    float r;
    asm("tanh.approx.f32 %0, %1;" : "=f"(r) : "f"(x));
    return r;
}
__device__ __forceinline__ uint32_t pack2(float a, float b) {
    __nv_bfloat162 t = __floats2bfloat162_rn(a, b);
    return *reinterpret_cast<uint32_t*>(&t);
}

// ---------------------------------------------------------------------------
// small kernels
// ---------------------------------------------------------------------------
__global__ void prep_w_kernel(const float* __restrict__ W, int ldw, int K,
                              __nv_bfloat16* __restrict__ hi, __nv_bfloat16* __restrict__ lo) {
    int n = blockIdx.x;
    for (int k = threadIdx.x; k < K; k += blockDim.x) {
        float f = W[(size_t)n * ldw + k];
        __nv_bfloat16 h = __float2bfloat16(f);
        hi[n * K + k] = h;
        lo[n * K + k] = __float2bfloat16(f - __bfloat162float(h));
    }
}

__global__ void mean_sum_x_kernel(const float* __restrict__ x, float* __restrict__ out) {
    int b = blockIdx.x, t = threadIdx.x;   // block 128
    const float* p = x + (size_t)b * S_LEN * 128 + t;
    float s = 0.f;
#pragma unroll 8
    for (int i = 0; i < S_LEN; i++) s += p[(size_t)i * 128];
    out[b * 128 + t] = s;
}

__global__ void cbias_kernel(const float* __restrict__ msum, const float* __restrict__ W,
                             const float* __restrict__ bias, float* __restrict__ c,
                             int K, int ldw, int koff) {
    __shared__ float ms[H_DIM];
    int b = blockIdx.x, h = threadIdx.x;
    if (h < K) ms[h] = msum[b * K + h] * (1.0f / S_LEN);
    __syncthreads();
    const float* wr = W + (size_t)h * ldw + koff;
    float s = bias[h];
#pragma unroll 8
    for (int k = 0; k < K; k++) s += ms[k] * wr[k];
    c[b * H_DIM + h] = s;
}

__global__ void zero_kernel(float* p, int n) {
    int i = blockIdx.x * 256 + threadIdx.x;
    if (i < n) p[i] = 0.f;
}

// ---------------------------------------------------------------------------
// Fused layer (mma.sync HMMA): per CTA: Out[128 x 128] block of
//   tanh(A[128 x K] * (Wh+Wl)[128 x K]^T + cbias), 3-term bf16 split.
// Also writes bf16 hi/lo activation planes and accumulates column sums.
// Grid: (M_ROWS/128, 2). 256 threads = 8 warps (4 in M x 2 in N), warp 32x64.
// ---------------------------------------------------------------------------
#define AHI_OFF 0
#define ALO_OFF 16384
#define WHI_OFF 32768
#define WLO_OFF 49152
#define SMEM_BYTES (1024 + 65536)

template<int K_TOTAL, bool A_FP32, bool FINAL>
__global__ __launch_bounds__(256, 2) void fused_layer_kernel(
    const float* __restrict__ Af,
    const __nv_bfloat16* __restrict__ Ahi, const __nv_bfloat16* __restrict__ Alo,
    const __nv_bfloat16* __restrict__ Whi, const __nv_bfloat16* __restrict__ Wlo,
    const float* __restrict__ Cb,
    __nv_bfloat16* __restrict__ Ohi, __nv_bfloat16* __restrict__ Olo,
    float* __restrict__ Osum)
{
    extern __shared__ char smem_raw[];
    char* tb = (char*)(((uintptr_t)smem_raw + 1023) & ~(uintptr_t)1023);
    const uint32_t sb = smem_u32(tb);

    const int tid  = threadIdx.x;
    const int wid  = tid >> 5;
    const int lane = tid & 31;
    const int warp_m = wid & 3;          // 4 warps in M (32 rows each)
    const int warp_n = wid >> 2;         // 2 warps in N (64 cols each)
    const int m0 = blockIdx.x * 128;
    const int n0 = blockIdx.y * 128;
    const int set = m0 >> 10;

    float acc[2][8][4];
#pragma unroll
    for (int a = 0; a < 2; a++)
#pragma unroll
        for (int b = 0; b < 8; b++)
#pragma unroll
            for (int c = 0; c < 4; c++) acc[a][b][c] = 0.f;

    // per-lane ldmatrix address components
    const int r16 = lane & 15;           // row within 16-row tile
    const int kb  = (lane >> 4) * 16;    // byte offset of k-half

    const int NCHUNK = K_TOTAL / 64;
    for (int ch = 0; ch < NCHUNK; ch++) {
        // ---- load A chunk (128 rows x 64 k) into SMEM hi/lo ----
        if (A_FP32) {
#pragma unroll
            for (int i = 0; i < 8; i++) {
                int g = i * 256 + tid;
                int r = g >> 4, q = g & 15;
                float4 v = *(const float4*)(Af + (size_t)(m0 + r) * K_TOTAL + ch * 64 + q * 4);
                __nv_bfloat16 h0 = __float2bfloat16(v.x), h1 = __float2bfloat16(v.y);
                __nv_bfloat16 h2 = __float2bfloat16(v.z), h3 = __float2bfloat16(v.w);
                uint2 hv, lv;
                hv.x = ((uint32_t)*(uint16_t*)&h0) | ((uint32_t)*(uint16_t*)&h1 << 16);
                hv.y = ((uint32_t)*(uint16_t*)&h2) | ((uint32_t)*(uint16_t*)&h3 << 16);
                lv.x = pack2(v.x - __bfloat162float(h0), v.y - __bfloat162float(h1));
                lv.y = pack2(v.z - __bfloat162float(h2), v.w - __bfloat162float(h3));
                uint32_t off = SW128((uint32_t)(r * 128 + q * 8));
                *(uint2*)(tb + AHI_OFF + off) = hv;
                *(uint2*)(tb + ALO_OFF + off) = lv;
            }
        } else {
#pragma unroll
            for (int i = 0; i < 4; i++) {
                int g = i * 256 + tid;
                int r = g >> 3, u = g & 7;
                size_t src = (size_t)(m0 + r) * K_TOTAL + ch * 64 + u * 8;
                uint32_t off = SW128((uint32_t)(r * 128 + u * 16));
                *(uint4*)(tb + AHI_OFF + off) = *(const uint4*)(Ahi + src);
                *(uint4*)(tb + ALO_OFF + off) = *(const uint4*)(Alo + src);
            }
        }
        // ---- load W chunk (128 N-rows x 64 k, pre-split bf16) ----
#pragma unroll
        for (int i = 0; i < 4; i++) {
            int g = i * 256 + tid;
            int r = g >> 3, u = g & 7;
            size_t src = (size_t)(n0 + r) * K_TOTAL + ch * 64 + u * 8;
            uint32_t off = SW128((uint32_t)(r * 128 + u * 16));
            *(uint4*)(tb + WHI_OFF + off) = *(const uint4*)(Whi + src);
            *(uint4*)(tb + WLO_OFF + off) = *(const uint4*)(Wlo + src);
        }
        __syncthreads();

        // ---- 4 k16 steps ----
#pragma unroll
        for (int kk = 0; kk < 4; kk++) {
            const uint32_t colb = (uint32_t)(kk * 32 + kb);
            uint32_t ah[2][4], al[2][4];
#pragma unroll
            for (int mt = 0; mt < 2; mt++) {
                uint32_t off = SW128((uint32_t)((warp_m * 32 + mt * 16 + r16) * 128) + colb);
                ldsm_x4(ah[mt], sb + AHI_OFF + off);
                ldsm_x4(al[mt], sb + ALO_OFF + off);
            }
#pragma unroll
            for (int p = 0; p < 4; p++) {
                uint32_t offB = SW128((uint32_t)((warp_n * 64 + p * 16 + r16) * 128) + colb);
                uint32_t bh[4], bl[4];
                ldsm_x4(bh, sb + WHI_OFF + offB);
                ldsm_x4(bl, sb + WLO_OFF + offB);
#pragma unroll
                for (int mt = 0; mt < 2; mt++) {
                    mma_bf16(acc[mt][2 * p],     ah[mt], bh[0], bh[2]);
                    mma_bf16(acc[mt][2 * p + 1], ah[mt], bh[1], bh[3]);
                    mma_bf16(acc[mt][2 * p],     ah[mt], bl[0], bl[2]);
                    mma_bf16(acc[mt][2 * p + 1], ah[mt], bl[1], bl[3]);
                    mma_bf16(acc[mt][2 * p],     al[mt], bh[0], bh[2]);
                    mma_bf16(acc[mt][2 * p + 1], al[mt], bh[1], bh[3]);
                }
            }
        }
        __syncthreads();
    }

    // ---- epilogue ----
    float* cbs = (float*)tb;    // reuse tile buffer
    if (tid < 128) cbs[tid] = Cb[set * 256 + n0 + tid];
    __syncthreads();

    const int lq = lane >> 2;           // 0..7 (row group)
    const int lr = lane & 3;            // 0..3 (col pair)

    float colsum[8][2];
#pragma unroll
    for (int nt = 0; nt < 8; nt++) { colsum[nt][0] = 0.f; colsum[nt][1] = 0.f; }

#pragma unroll
    for (int mt = 0; mt < 2; mt++) {
        const int rbase = m0 + warp_m * 32 + mt * 16 + lq;
#pragma unroll
        for (int nt = 0; nt < 8; nt++) {
            const int lc = warp_n * 64 + nt * 8 + 2 * lr;   // local col in [0,128)
            float v0 = tanh_fast(acc[mt][nt][0] + cbs[lc]);
            float v1 = tanh_fast(acc[mt][nt][1] + cbs[lc + 1]);
            float v2 = tanh_fast(acc[mt][nt][2] + cbs[lc]);
            float v3 = tanh_fast(acc[mt][nt][3] + cbs[lc + 1]);
            colsum[nt][0] += v0 + v2;
            colsum[nt][1] += v1 + v3;
            if (!FINAL) {
                size_t o0 = (size_t)rbase * 256 + n0 + lc;
                size_t o1 = (size_t)(rbase + 8) * 256 + n0 + lc;
                *(uint32_t*)(Ohi + o0) = pack2(v0, v1);
                *(uint32_t*)(Ohi + o1) = pack2(v2, v3);
                *(uint32_t*)(Olo + o0) = pack2(v0 - __bfloat162float(__float2bfloat16(v0)),
                                               v1 - __bfloat162float(__float2bfloat16(v1)));
                *(uint32_t*)(Olo + o1) = pack2(v2 - __bfloat162float(__float2bfloat16(v2)),
                                               v3 - __bfloat162float(__float2bfloat16(v3)));
            }
        }
    }
    // reduce column sums over row-groups (lanes differing in bits 2..4)
#pragma unroll
    for (int nt = 0; nt < 8; nt++) {
#pragma unroll
        for (int h = 0; h < 2; h++) {
            float s = colsum[nt][h];
            s += __shfl_xor_sync(0xffffffffu, s, 4);
            s += __shfl_xor_sync(0xffffffffu, s, 8);
            s += __shfl_xor_sync(0xffffffffu, s, 16);
            if (lq == 0) {
                int gc = n0 + warp_n * 64 + nt * 8 + 2 * lr + h;
                atomicAdd(Osum + set * 256 + gc, FINAL ? s * (1.0f / S_LEN) : s);
            }
        }
    }
}

// ---------------------------------------------------------------------------
extern "C" void kernel_launch(void* const* d_in, const int* in_sizes, int n_in,
                              void* d_out, int out_size) {
    const float* x  = (const float*)d_in[0];
    const float* W0 = (const float*)d_in[1];
    const float* b0 = (const float*)d_in[2];
    const float* W1 = (const float*)d_in[3];
    const float* b1 = (const float*)d_in[4];
    const float* W2 = (const float*)d_in[5];
    const float* b2 = (const float*)d_in[6];
    float* out = (float*)d_out;

    __nv_bfloat16 *hi1, *lo1, *hi2, *lo2, *whi0, *wlo0, *whi1, *wlo1, *whi2, *wlo2;
    float *msum, *cb;
    cudaGetSymbolAddress((void**)&hi1, g_hi1);
    cudaGetSymbolAddress((void**)&lo1, g_lo1);
    cudaGetSymbolAddress((void**)&hi2, g_hi2);
    cudaGetSymbolAddress((void**)&lo2, g_lo2);
    cudaGetSymbolAddress((void**)&whi0, g_whi0);
    cudaGetSymbolAddress((void**)&wlo0, g_wlo0);
    cudaGetSymbolAddress((void**)&whi1, g_whi1);
    cudaGetSymbolAddress((void**)&wlo1, g_wlo1);
    cudaGetSymbolAddress((void**)&whi2, g_whi2);
    cudaGetSymbolAddress((void**)&wlo2, g_wlo2);
    cudaGetSymbolAddress((void**)&msum, g_msum);
    cudaGetSymbolAddress((void**)&cb,   g_cb);

    cudaFuncSetAttribute(fused_layer_kernel<128, true,  false>,
                         cudaFuncAttributeMaxDynamicSharedMemorySize, SMEM_BYTES);
    cudaFuncSetAttribute(fused_layer_kernel<256, false, false>,
                         cudaFuncAttributeMaxDynamicSharedMemorySize, SMEM_BYTES);
    cudaFuncSetAttribute(fused_layer_kernel<256, false, true>,
                         cudaFuncAttributeMaxDynamicSharedMemorySize, SMEM_BYTES);

    dim3 gg(M_ROWS / 128, 2);

    // weight pre-split (bf16 hi/lo)
    prep_w_kernel<<<H_DIM, 256>>>(W0, 256, 128, whi0, wlo0);
    prep_w_kernel<<<H_DIM, 256>>>(W1, 512, 256, whi1, wlo1);
    prep_w_kernel<<<H_DIM, 256>>>(W2, 512, 256, whi2, wlo2);

    // Layer 0
    mean_sum_x_kernel<<<B_SETS, 128>>>(x, msum);
    cbias_kernel<<<B_SETS, H_DIM>>>(msum, W0, b0, cb, 128, 256, 128);
    zero_kernel<<<B_SETS, 256>>>(msum, B_SETS * H_DIM);
    fused_layer_kernel<128, true, false><<<gg, 256, SMEM_BYTES>>>(
        x, nullptr, nullptr, whi0, wlo0, cb, hi1, lo1, msum);

    // Layer 1
    cbias_kernel<<<B_SETS, H_DIM>>>(msum, W1, b1, cb, 256, 512, 256);
    zero_kernel<<<B_SETS, 256>>>(msum, B_SETS * H_DIM);
    fused_layer_kernel<256, false, false><<<gg, 256, SMEM_BYTES>>>(
        nullptr, hi1, lo1, whi1, wlo1, cb, hi2, lo2, msum);

    // Layer 2 (final): mean of tanh goes straight to out
    cbias_kernel<<<B_SETS, H_DIM>>>(msum, W2, b2, cb, 256, 512, 256);
    zero_kernel<<<B_SETS, 256>>>(out, B_SETS * H_DIM);
    fused_layer_kernel<256, false, true><<<gg, 256, SMEM_BYTES>>>(
        nullptr, hi2, lo2, whi2, wlo2, cb, nullptr, nullptr, out);
}

// round 5
// speedup vs baseline: 2.5592x; 1.1020x over previous
#include <cuda_runtime.h>
#include <cuda_bf16.h>
#include <cstdint>

#define B_SETS 256
#define S_LEN  1024
#define H_DIM  256
#define M_ROWS (B_SETS * S_LEN)

// ---------------------------------------------------------------------------
// Scratch (__device__ globals; allocation-free rule)
// ---------------------------------------------------------------------------
__device__ __nv_bfloat16 g_hi1[(size_t)M_ROWS * H_DIM];
__device__ __nv_bfloat16 g_lo1[(size_t)M_ROWS * H_DIM];
__device__ __nv_bfloat16 g_hi2[(size_t)M_ROWS * H_DIM];   // also x-planes for L0
__device__ __nv_bfloat16 g_lo2[(size_t)M_ROWS * H_DIM];
__device__ __nv_bfloat16 g_whi0[H_DIM * 128], g_wlo0[H_DIM * 128];
__device__ __nv_bfloat16 g_whi1[H_DIM * H_DIM], g_wlo1[H_DIM * H_DIM];
__device__ __nv_bfloat16 g_whi2[H_DIM * H_DIM], g_wlo2[H_DIM * H_DIM];
__device__ float g_msum[B_SETS * H_DIM];   // column sums (per set)
__device__ float g_cb[B_SETS * H_DIM];     // per-set bias c[b,h]

// ---------------------------------------------------------------------------
// helpers
// ---------------------------------------------------------------------------
__device__ __forceinline__ uint32_t smem_u32(const void* p) {
    uint32_t a;
    asm("{ .reg .u64 t; cvta.to.shared.u64 t, %1; cvt.u32.u64 %0, t; }" : "=r"(a) : "l"(p));
    return a;
}
// SW64 swizzle for 64-byte rows (8-row atom)
#define SW64(o) ((uint32_t)(o) ^ ((((uint32_t)(o)) >> 3) & 0x30u))

__device__ __forceinline__ void ldsm_x4(uint32_t* r, uint32_t addr) {
    asm volatile("ldmatrix.sync.aligned.m8n8.x4.shared.b16 {%0,%1,%2,%3}, [%4];"
                 : "=r"(r[0]), "=r"(r[1]), "=r"(r[2]), "=r"(r[3]) : "r"(addr));
}
__device__ __forceinline__ void mma_bf16(float* d, const uint32_t* a, uint32_t b0, uint32_t b1) {
    asm volatile(
        "mma.sync.aligned.m16n8k16.row.col.f32.bf16.bf16.f32 "
        "{%0,%1,%2,%3},{%4,%5,%6,%7},{%8,%9},{%0,%1,%2,%3};"
        : "+f"(d[0]), "+f"(d[1]), "+f"(d[2]), "+f"(d[3])
        : "r"(a[0]), "r"(a[1]), "r"(a[2]), "r"(a[3]), "r"(b0), "r"(b1));
}
__device__ __forceinline__ float tanh_fast(float x) {
    float r;
    asm("tanh.approx.f32 %0, %1;" : "=f"(r) : "f"(x));
    return r;
}
__device__ __forceinline__ uint32_t pack2(float a, float b) {
    __nv_bfloat162 t = __floats2bfloat162_rn(a, b);
    return *reinterpret_cast<uint32_t*>(&t);
}
__device__ __forceinline__ void cpa16(uint32_t dst, const void* src) {
    asm volatile("cp.async.cg.shared.global [%0], [%1], 16;" :: "r"(dst), "l"(src));
}
__device__ __forceinline__ void cpa_commit() {
    asm volatile("cp.async.commit_group;");
}
template<int N>
__device__ __forceinline__ void cpa_wait() {
    asm volatile("cp.async.wait_group %0;" :: "n"(N));
}

// ---------------------------------------------------------------------------
// small kernels
// ---------------------------------------------------------------------------
__global__ void prep_w_kernel(const float* __restrict__ W, int ldw, int K,
                              __nv_bfloat16* __restrict__ hi, __nv_bfloat16* __restrict__ lo) {
    int n = blockIdx.x;
    for (int k = threadIdx.x; k < K; k += blockDim.x) {
        float f = W[(size_t)n * ldw + k];
        __nv_bfloat16 h = __float2bfloat16(f);
        hi[n * K + k] = h;
        lo[n * K + k] = __float2bfloat16(f - __bfloat162float(h));
    }
}

// x fp32 -> bf16 hi/lo planes (vectorized)
__global__ void prep_x_kernel(const float* __restrict__ x,
                              __nv_bfloat16* __restrict__ hi, __nv_bfloat16* __restrict__ lo) {
    size_t i = ((size_t)blockIdx.x * 256 + threadIdx.x) * 4;
    float4 v = *(const float4*)(x + i);
    __nv_bfloat16 h0 = __float2bfloat16(v.x), h1 = __float2bfloat16(v.y);
    __nv_bfloat16 h2 = __float2bfloat16(v.z), h3 = __float2bfloat16(v.w);
    uint2 hv, lv;
    hv.x = ((uint32_t)*(uint16_t*)&h0) | ((uint32_t)*(uint16_t*)&h1 << 16);
    hv.y = ((uint32_t)*(uint16_t*)&h2) | ((uint32_t)*(uint16_t*)&h3 << 16);
    lv.x = pack2(v.x - __bfloat162float(h0), v.y - __bfloat162float(h1));
    lv.y = pack2(v.z - __bfloat162float(h2), v.w - __bfloat162float(h3));
    *(uint2*)(hi + i) = hv;
    *(uint2*)(lo + i) = lv;
}

// partial mean: grid (B_SETS, 8), block 128 — atomicAdd into msum (pre-zeroed)
__global__ void mean_sum_x_kernel(const float* __restrict__ x, float* __restrict__ out) {
    int b = blockIdx.x, cz = blockIdx.y, t = threadIdx.x;
    const float* p = x + (size_t)b * S_LEN * 128 + (size_t)cz * 128 * 128 + t;
    float s = 0.f;
#pragma unroll 8
    for (int i = 0; i < 128; i++) s += p[(size_t)i * 128];
    atomicAdd(out + b * 128 + t, s);
}

__global__ void cbias_kernel(const float* __restrict__ msum, const float* __restrict__ W,
                             const float* __restrict__ bias, float* __restrict__ c,
                             int K, int ldw, int koff) {
    __shared__ float ms[H_DIM];
    int b = blockIdx.x, h = threadIdx.x;
    if (h < K) ms[h] = msum[b * K + h] * (1.0f / S_LEN);
    __syncthreads();
    const float* wr = W + (size_t)h * ldw + koff;
    float s = bias[h];
#pragma unroll 8
    for (int k = 0; k < K; k++) s += ms[k] * wr[k];
    c[b * H_DIM + h] = s;
}

__global__ void zero_kernel(float* p, int n) {
    int i = blockIdx.x * 256 + threadIdx.x;
    if (i < n) p[i] = 0.f;
}

// ---------------------------------------------------------------------------
// Fused layer (HMMA, cp.async 2-stage pipeline):
// CTA computes Out[128 x 128] = tanh(A[128xK] (Wh+Wl)[128xK]^T + cbias),
// 3-term bf16 split, writes bf16 hi/lo planes, accumulates column sums.
// K chunked by 32 (rows of 64 bytes, SW64 swizzle). 8 warps: 4 in M x 2 in N.
// ---------------------------------------------------------------------------
#define A_HI 0
#define A_LO 8192
#define W_HI 16384
#define W_LO 24576
#define STAGE_BYTES 32768
#define SMEM_BYTES  (2 * STAGE_BYTES)

template<int K_TOTAL, bool FINAL>
__global__ __launch_bounds__(256, 2) void fused_layer_kernel(
    const __nv_bfloat16* __restrict__ Ahi, const __nv_bfloat16* __restrict__ Alo,
    const __nv_bfloat16* __restrict__ Whi, const __nv_bfloat16* __restrict__ Wlo,
    const float* __restrict__ Cb,
    __nv_bfloat16* __restrict__ Ohi, __nv_bfloat16* __restrict__ Olo,
    float* __restrict__ Osum)
{
    extern __shared__ char smem_raw[];
    char* tb = smem_raw;
    const uint32_t sb = smem_u32(tb);

    const int tid  = threadIdx.x;
    const int wid  = tid >> 5;
    const int lane = tid & 31;
    const int warp_m = wid & 3;
    const int warp_n = wid >> 2;
    const int m0 = blockIdx.x * 128;
    const int n0 = blockIdx.y * 128;
    const int set = m0 >> 10;

    float acc[2][8][4];
#pragma unroll
    for (int a = 0; a < 2; a++)
#pragma unroll
        for (int b = 0; b < 8; b++)
#pragma unroll
            for (int c = 0; c < 4; c++) acc[a][b][c] = 0.f;

    const int NCHUNK = K_TOTAL / 32;

    // loader lambda-ish: issue cp.async for chunk ch into stage st
    // per plane: 128 rows x 64B = 512 x 16B units; 256 threads x 2 units
    const int u0 = tid;                 // unit ids tid and tid+256
    auto issue_chunk = [&](int ch, int st) {
        const uint32_t sbase = sb + st * STAGE_BYTES;
#pragma unroll
        for (int i = 0; i < 2; i++) {
            int u = i * 256 + u0;
            int row = u >> 2, c16 = u & 3;
            uint32_t doff = SW64(row * 64 + c16 * 16);
            size_t asrc = (size_t)(m0 + row) * K_TOTAL + ch * 32 + c16 * 8;
            size_t wsrc = (size_t)(n0 + row) * K_TOTAL + ch * 32 + c16 * 8;
            cpa16(sbase + A_HI + doff, Ahi + asrc);
            cpa16(sbase + A_LO + doff, Alo + asrc);
            cpa16(sbase + W_HI + doff, Whi + wsrc);
            cpa16(sbase + W_LO + doff, Wlo + wsrc);
        }
        cpa_commit();
    };

    issue_chunk(0, 0);

    const int r16 = lane & 15;
    const int kb  = (lane >> 4) * 16;

    for (int ch = 0; ch < NCHUNK; ch++) {
        const int st = ch & 1;
        if (ch + 1 < NCHUNK) {
            issue_chunk(ch + 1, st ^ 1);
            cpa_wait<1>();
        } else {
            cpa_wait<0>();
        }
        __syncthreads();

        const uint32_t sbase = sb + st * STAGE_BYTES;
#pragma unroll
        for (int kk = 0; kk < 2; kk++) {
            const uint32_t colb = (uint32_t)(kk * 32 + kb);
            uint32_t ah[2][4], al[2][4];
#pragma unroll
            for (int mt = 0; mt < 2; mt++) {
                uint32_t off = SW64((warp_m * 32 + mt * 16 + r16) * 64 + colb);
                ldsm_x4(ah[mt], sbase + A_HI + off);
                ldsm_x4(al[mt], sbase + A_LO + off);
            }
#pragma unroll
            for (int p = 0; p < 4; p++) {
                uint32_t offB = SW64((warp_n * 64 + p * 16 + r16) * 64 + colb);
                uint32_t bh[4], bl[4];
                ldsm_x4(bh, sbase + W_HI + offB);
                ldsm_x4(bl, sbase + W_LO + offB);
#pragma unroll
                for (int mt = 0; mt < 2; mt++) {
                    mma_bf16(acc[mt][2 * p],     ah[mt], bh[0], bh[2]);
                    mma_bf16(acc[mt][2 * p + 1], ah[mt], bh[1], bh[3]);
                    mma_bf16(acc[mt][2 * p],     ah[mt], bl[0], bl[2]);
                    mma_bf16(acc[mt][2 * p + 1], ah[mt], bl[1], bl[3]);
                    mma_bf16(acc[mt][2 * p],     al[mt], bh[0], bh[2]);
                    mma_bf16(acc[mt][2 * p + 1], al[mt], bh[1], bh[3]);
                }
            }
        }
        __syncthreads();
    }

    // ---- epilogue ----
    float* cbs = (float*)tb;
    if (tid < 128) cbs[tid] = Cb[set * 256 + n0 + tid];
    __syncthreads();

    const int lq = lane >> 2;
    const int lr = lane & 3;

    float colsum[8][2];
#pragma unroll
    for (int nt = 0; nt < 8; nt++) { colsum[nt][0] = 0.f; colsum[nt][1] = 0.f; }

#pragma unroll
    for (int mt = 0; mt < 2; mt++) {
        const int rbase = m0 + warp_m * 32 + mt * 16 + lq;
#pragma unroll
        for (int nt = 0; nt < 8; nt++) {
            const int lc = warp_n * 64 + nt * 8 + 2 * lr;
            float v0 = tanh_fast(acc[mt][nt][0] + cbs[lc]);
            float v1 = tanh_fast(acc[mt][nt][1] + cbs[lc + 1]);
            float v2 = tanh_fast(acc[mt][nt][2] + cbs[lc]);
            float v3 = tanh_fast(acc[mt][nt][3] + cbs[lc + 1]);
            colsum[nt][0] += v0 + v2;
            colsum[nt][1] += v1 + v3;
            if (!FINAL) {
                size_t o0 = (size_t)rbase * 256 + n0 + lc;
                size_t o1 = (size_t)(rbase + 8) * 256 + n0 + lc;
                *(uint32_t*)(Ohi + o0) = pack2(v0, v1);
                *(uint32_t*)(Ohi + o1) = pack2(v2, v3);
                *(uint32_t*)(Olo + o0) = pack2(v0 - __bfloat162float(__float2bfloat16(v0)),
                                               v1 - __bfloat162float(__float2bfloat16(v1)));
                *(uint32_t*)(Olo + o1) = pack2(v2 - __bfloat162float(__float2bfloat16(v2)),
                                               v3 - __bfloat162float(__float2bfloat16(v3)));
            }
        }
    }
#pragma unroll
    for (int nt = 0; nt < 8; nt++) {
#pragma unroll
        for (int h = 0; h < 2; h++) {
            float s = colsum[nt][h];
            s += __shfl_xor_sync(0xffffffffu, s, 4);
            s += __shfl_xor_sync(0xffffffffu, s, 8);
            s += __shfl_xor_sync(0xffffffffu, s, 16);
            if (lq == 0) {
                int gc = n0 + warp_n * 64 + nt * 8 + 2 * lr + h;
                atomicAdd(Osum + set * 256 + gc, FINAL ? s * (1.0f / S_LEN) : s);
            }
        }
    }
}

// ---------------------------------------------------------------------------
extern "C" void kernel_launch(void* const* d_in, const int* in_sizes, int n_in,
                              void* d_out, int out_size) {
    const float* x  = (const float*)d_in[0];
    const float* W0 = (const float*)d_in[1];
    const float* b0 = (const float*)d_in[2];
    const float* W1 = (const float*)d_in[3];
    const float* b1 = (const float*)d_in[4];
    const float* W2 = (const float*)d_in[5];
    const float* b2 = (const float*)d_in[6];
    float* out = (float*)d_out;

    __nv_bfloat16 *hi1, *lo1, *hi2, *lo2, *whi0, *wlo0, *whi1, *wlo1, *whi2, *wlo2;
    float *msum, *cb;
    cudaGetSymbolAddress((void**)&hi1, g_hi1);
    cudaGetSymbolAddress((void**)&lo1, g_lo1);
    cudaGetSymbolAddress((void**)&hi2, g_hi2);
    cudaGetSymbolAddress((void**)&lo2, g_lo2);
    cudaGetSymbolAddress((void**)&whi0, g_whi0);
    cudaGetSymbolAddress((void**)&wlo0, g_wlo0);
    cudaGetSymbolAddress((void**)&whi1, g_whi1);
    cudaGetSymbolAddress((void**)&wlo1, g_wlo1);
    cudaGetSymbolAddress((void**)&whi2, g_whi2);
    cudaGetSymbolAddress((void**)&wlo2, g_wlo2);
    cudaGetSymbolAddress((void**)&msum, g_msum);
    cudaGetSymbolAddress((void**)&cb,   g_cb);

    cudaFuncSetAttribute(fused_layer_kernel<128, false>,
                         cudaFuncAttributeMaxDynamicSharedMemorySize, SMEM_BYTES);
    cudaFuncSetAttribute(fused_layer_kernel<256, false>,
                         cudaFuncAttributeMaxDynamicSharedMemorySize, SMEM_BYTES);
    cudaFuncSetAttribute(fused_layer_kernel<256, true>,
                         cudaFuncAttributeMaxDynamicSharedMemorySize, SMEM_BYTES);

    dim3 gg(M_ROWS / 128, 2);

    // prep: weights + x planes (x planes live in g_hi2/g_lo2)
    prep_w_kernel<<<H_DIM, 256>>>(W0, 256, 128, whi0, wlo0);
    prep_w_kernel<<<H_DIM, 256>>>(W1, 512, 256, whi1, wlo1);
    prep_w_kernel<<<H_DIM, 256>>>(W2, 512, 256, whi2, wlo2);
    prep_x_kernel<<<(M_ROWS * 128) / 1024, 256>>>(x, hi2, lo2);

    // Layer 0
    zero_kernel<<<B_SETS, 256>>>(msum, B_SETS * H_DIM);
    mean_sum_x_kernel<<<dim3(B_SETS, 8), 128>>>(x, msum);
    cbias_kernel<<<B_SETS, H_DIM>>>(msum, W0, b0, cb, 128, 256, 128);
    zero_kernel<<<B_SETS, 256>>>(msum, B_SETS * H_DIM);
    fused_layer_kernel<128, false><<<gg, 256, SMEM_BYTES>>>(
        hi2, lo2, whi0, wlo0, cb, hi1, lo1, msum);

    // Layer 1 (reads hi1/lo1, writes hi2/lo2 — x planes no longer needed)
    cbias_kernel<<<B_SETS, H_DIM>>>(msum, W1, b1, cb, 256, 512, 256);
    zero_kernel<<<B_SETS, 256>>>(msum, B_SETS * H_DIM);
    fused_layer_kernel<256, false><<<gg, 256, SMEM_BYTES>>>(
        hi1, lo1, whi1, wlo1, cb, hi2, lo2, msum);

    // Layer 2 (final)
    cbias_kernel<<<B_SETS, H_DIM>>>(msum, W2, b2, cb, 256, 512, 256);
    zero_kernel<<<B_SETS, 256>>>(out, B_SETS * H_DIM);
    fused_layer_kernel<256, true><<<gg, 256, SMEM_BYTES>>>(
        hi2, lo2, whi2, wlo2, cb, nullptr, nullptr, out);
}

// round 8
// speedup vs baseline: 3.5100x; 1.3715x over previous
#include <cuda_runtime.h>
#include <cuda_fp16.h>
#include <cstdint>

#define B_SETS 256
#define S_LEN  1024
#define H_DIM  256
#define M_ROWS (B_SETS * S_LEN)

// ---------------------------------------------------------------------------
// Scratch (__device__ globals; allocation-free rule)
// ---------------------------------------------------------------------------
__device__ __half g_act1[(size_t)M_ROWS * H_DIM];  // 128 MB
__device__ __half g_act2[(size_t)M_ROWS * H_DIM];  // 128 MB (x plane for L0)
__device__ __half g_whi0[H_DIM * 128], g_wlo0[H_DIM * 128];
__device__ __half g_whi1[H_DIM * H_DIM], g_wlo1[H_DIM * H_DIM];
__device__ __half g_whi2[H_DIM * H_DIM], g_wlo2[H_DIM * H_DIM];
__device__ float g_msum[B_SETS * H_DIM];   // column sums (per set)
__device__ float g_cb[B_SETS * H_DIM];     // per-set bias c[b,h]

// ---------------------------------------------------------------------------
// helpers
// ---------------------------------------------------------------------------
__device__ __forceinline__ uint32_t smem_u32(const void* p) {
    uint32_t a;
    asm("{ .reg .u64 t; cvta.to.shared.u64 t, %1; cvt.u32.u64 %0, t; }" : "=r"(a) : "l"(p));
    return a;
}
#define SW128(o) ((uint32_t)(o) ^ ((((uint32_t)(o)) >> 3) & 0x70u))

__device__ __forceinline__ void ldsm_x4(uint32_t* r, uint32_t addr) {
    asm volatile("ldmatrix.sync.aligned.m8n8.x4.shared.b16 {%0,%1,%2,%3}, [%4];"
                 : "=r"(r[0]), "=r"(r[1]), "=r"(r[2]), "=r"(r[3]) : "r"(addr));
}
__device__ __forceinline__ void mma_fp16(float* d, const uint32_t* a, uint32_t b0, uint32_t b1) {
    asm volatile(
        "mma.sync.aligned.m16n8k16.row.col.f32.f16.f16.f32 "
        "{%0,%1,%2,%3},{%4,%5,%6,%7},{%8,%9},{%0,%1,%2,%3};"
        : "+f"(d[0]), "+f"(d[1]), "+f"(d[2]), "+f"(d[3])
        : "r"(a[0]), "r"(a[1]), "r"(a[2]), "r"(a[3]), "r"(b0), "r"(b1));
}
__device__ __forceinline__ float tanh_fast(float x) {
    float r;
    asm("tanh.approx.f32 %0, %1;" : "=f"(r) : "f"(x));
    return r;
}
__device__ __forceinline__ uint32_t pack2h(float a, float b) {
    __half2 t = __floats2half2_rn(a, b);
    return *reinterpret_cast<uint32_t*>(&t);
}
__device__ __forceinline__ void cpa16(uint32_t dst, const void* src) {
    asm volatile("cp.async.cg.shared.global [%0], [%1], 16;" :: "r"(dst), "l"(src));
}
__device__ __forceinline__ void cpa_commit() {
    asm volatile("cp.async.commit_group;");
}
template<int N>
__device__ __forceinline__ void cpa_wait() {
    asm volatile("cp.async.wait_group %0;" :: "n"(N));
}

// ---------------------------------------------------------------------------
// small kernels
// ---------------------------------------------------------------------------
__global__ void prep_w_kernel(const float* __restrict__ W, int ldw, int K,
                              __half* __restrict__ hi, __half* __restrict__ lo) {
    int n = blockIdx.x;
    for (int k = threadIdx.x; k < K; k += blockDim.x) {
        float f = W[(size_t)n * ldw + k];
        __half h = __float2half_rn(f);
        hi[n * K + k] = h;
        lo[n * K + k] = __float2half_rn(f - __half2float(h));
    }
}

// x fp32 -> single fp16 plane (vectorized, 8 elems/thread)
__global__ void prep_x_kernel(const float* __restrict__ x, __half* __restrict__ hi) {
    size_t i = ((size_t)blockIdx.x * 256 + threadIdx.x) * 8;
    float4 v0 = *(const float4*)(x + i);
    float4 v1 = *(const float4*)(x + i + 4);
    uint4 h;
    h.x = pack2h(v0.x, v0.y);
    h.y = pack2h(v0.z, v0.w);
    h.z = pack2h(v1.x, v1.y);
    h.w = pack2h(v1.z, v1.w);
    *(uint4*)(hi + i) = h;
}

// partial mean: grid (B_SETS, 8), block 128 — atomicAdd into msum (pre-zeroed)
__global__ void mean_sum_x_kernel(const float* __restrict__ x, float* __restrict__ out) {
    int b = blockIdx.x, cz = blockIdx.y, t = threadIdx.x;
    const float* p = x + (size_t)b * S_LEN * 128 + (size_t)cz * 128 * 128 + t;
    float s = 0.f;
#pragma unroll 8
    for (int i = 0; i < 128; i++) s += p[(size_t)i * 128];
    atomicAdd(out + b * 128 + t, s);
}

__global__ void cbias_kernel(const float* __restrict__ msum, const float* __restrict__ W,
                             const float* __restrict__ bias, float* __restrict__ c,
                             int K, int ldw, int koff) {
    __shared__ float ms[H_DIM];
    int b = blockIdx.x, h = threadIdx.x;
    if (h < K) ms[h] = msum[b * K + h] * (1.0f / S_LEN);
    __syncthreads();
    const float* wr = W + (size_t)h * ldw + koff;
    float s = bias[h];
#pragma unroll 8
    for (int k = 0; k < K; k++) s += ms[k] * wr[k];
    c[b * H_DIM + h] = s;
}

__global__ void zero_kernel(float* p, int n) {
    int i = blockIdx.x * 256 + threadIdx.x;
    if (i < n) p[i] = 0.f;
}

// ---------------------------------------------------------------------------
// Fused layer (fp16 HMMA, cp.async 2-stage pipeline, 2-term W split):
// CTA: Out[128 x 128] = tanh(A[128xK] (Wh+Wl)[128xK]^T + cbias)
// A single fp16 plane; W pre-split hi/lo fp16. K chunk 64 (128B rows, SW128).
// 8 warps: 4 in M x 2 in N. Writes fp16 activations, accumulates column sums.
// ---------------------------------------------------------------------------
#define A_PL 0
#define W_HI 16384
#define W_LO 32768
#define STAGE_BYTES 49152
#define SMEM_BYTES  (2 * STAGE_BYTES)

template<int K_TOTAL, bool FINAL>
__global__ __launch_bounds__(256, 2) void fused_layer_kernel(
    const __half* __restrict__ A,
    const __half* __restrict__ Whi, const __half* __restrict__ Wlo,
    const float* __restrict__ Cb,
    __half* __restrict__ Oact,
    float* __restrict__ Osum)
{
    extern __shared__ char smem_raw[];
    char* tb = smem_raw;
    const uint32_t sb = smem_u32(tb);

    const int tid  = threadIdx.x;
    const int wid  = tid >> 5;
    const int lane = tid & 31;
    const int warp_m = wid & 3;
    const int warp_n = wid >> 2;
    const int m0 = blockIdx.x * 128;
    const int n0 = blockIdx.y * 128;
    const int set = m0 >> 10;

    float acc[2][8][4];
#pragma unroll
    for (int a = 0; a < 2; a++)
#pragma unroll
        for (int b = 0; b < 8; b++)
#pragma unroll
            for (int c = 0; c < 4; c++) acc[a][b][c] = 0.f;

    const int NCHUNK = K_TOTAL / 64;

    // issue cp.async for chunk ch into stage st
    // per plane: 128 rows x 128B = 1024 x 16B units; 256 threads -> 4 units each
    auto issue_chunk = [&](int ch, int st) {
        const uint32_t sbase = sb + st * STAGE_BYTES;
#pragma unroll
        for (int i = 0; i < 4; i++) {
            int u = i * 256 + tid;
            int row = u >> 3, c16 = u & 7;
            uint32_t doff = SW128(row * 128 + c16 * 16);
            size_t asrc = (size_t)(m0 + row) * K_TOTAL + ch * 64 + c16 * 8;
            size_t wsrc = (size_t)(n0 + row) * K_TOTAL + ch * 64 + c16 * 8;
            cpa16(sbase + A_PL + doff, A + asrc);
            cpa16(sbase + W_HI + doff, Whi + wsrc);
            cpa16(sbase + W_LO + doff, Wlo + wsrc);
        }
        cpa_commit();
    };

    issue_chunk(0, 0);

    const int r16 = lane & 15;
    const int kb  = (lane >> 4) * 16;

    for (int ch = 0; ch < NCHUNK; ch++) {
        const int st = ch & 1;
        if (ch + 1 < NCHUNK) {
            issue_chunk(ch + 1, st ^ 1);
            cpa_wait<1>();
        } else {
            cpa_wait<0>();
        }
        __syncthreads();

        const uint32_t sbase = sb + st * STAGE_BYTES;
#pragma unroll
        for (int kk = 0; kk < 4; kk++) {
            const uint32_t colb = (uint32_t)(kk * 32 + kb);
            uint32_t ah[2][4];
#pragma unroll
            for (int mt = 0; mt < 2; mt++) {
                uint32_t off = SW128((warp_m * 32 + mt * 16 + r16) * 128 + colb);
                ldsm_x4(ah[mt], sbase + A_PL + off);
            }
#pragma unroll
            for (int p = 0; p < 4; p++) {
                uint32_t offB = SW128((warp_n * 64 + p * 16 + r16) * 128 + colb);
                uint32_t bh[4], bl[4];
                ldsm_x4(bh, sbase + W_HI + offB);
                ldsm_x4(bl, sbase + W_LO + offB);
#pragma unroll
                for (int mt = 0; mt < 2; mt++) {
                    mma_fp16(acc[mt][2 * p],     ah[mt], bh[0], bh[2]);
                    mma_fp16(acc[mt][2 * p + 1], ah[mt], bh[1], bh[3]);
                    mma_fp16(acc[mt][2 * p],     ah[mt], bl[0], bl[2]);
                    mma_fp16(acc[mt][2 * p + 1], ah[mt], bl[1], bl[3]);
                }
            }
        }
        __syncthreads();
    }

    // ---- epilogue ----
    float* cbs = (float*)tb;
    if (tid < 128) cbs[tid] = Cb[set * 256 + n0 + tid];
    __syncthreads();

    const int lq = lane >> 2;
    const int lr = lane & 3;

    float colsum[8][2];
#pragma unroll
    for (int nt = 0; nt < 8; nt++) { colsum[nt][0] = 0.f; colsum[nt][1] = 0.f; }

#pragma unroll
    for (int mt = 0; mt < 2; mt++) {
        const int rbase = m0 + warp_m * 32 + mt * 16 + lq;
#pragma unroll
        for (int nt = 0; nt < 8; nt++) {
            const int lc = warp_n * 64 + nt * 8 + 2 * lr;
            float v0 = tanh_fast(acc[mt][nt][0] + cbs[lc]);
            float v1 = tanh_fast(acc[mt][nt][1] + cbs[lc + 1]);
            float v2 = tanh_fast(acc[mt][nt][2] + cbs[lc]);
            float v3 = tanh_fast(acc[mt][nt][3] + cbs[lc + 1]);
            colsum[nt][0] += v0 + v2;
            colsum[nt][1] += v1 + v3;
            if (!FINAL) {
                *(uint32_t*)(Oact + (size_t)rbase * 256 + n0 + lc)       = pack2h(v0, v1);
                *(uint32_t*)(Oact + (size_t)(rbase + 8) * 256 + n0 + lc) = pack2h(v2, v3);
            }
        }
    }
#pragma unroll
    for (int nt = 0; nt < 8; nt++) {
#pragma unroll
        for (int h = 0; h < 2; h++) {
            float s = colsum[nt][h];
            s += __shfl_xor_sync(0xffffffffu, s, 4);
            s += __shfl_xor_sync(0xffffffffu, s, 8);
            s += __shfl_xor_sync(0xffffffffu, s, 16);
            if (lq == 0) {
                int gc = n0 + warp_n * 64 + nt * 8 + 2 * lr + h;
                atomicAdd(Osum + set * 256 + gc, FINAL ? s * (1.0f / S_LEN) : s);
            }
        }
    }
}

// ---------------------------------------------------------------------------
extern "C" void kernel_launch(void* const* d_in, const int* in_sizes, int n_in,
                              void* d_out, int out_size) {
    const float* x  = (const float*)d_in[0];
    const float* W0 = (const float*)d_in[1];
    const float* b0 = (const float*)d_in[2];
    const float* W1 = (const float*)d_in[3];
    const float* b1 = (const float*)d_in[4];
    const float* W2 = (const float*)d_in[5];
    const float* b2 = (const float*)d_in[6];
    float* out = (float*)d_out;

    __half *act1, *act2, *whi0, *wlo0, *whi1, *wlo1, *whi2, *wlo2;
    float *msum, *cb;
    cudaGetSymbolAddress((void**)&act1, g_act1);
    cudaGetSymbolAddress((void**)&act2, g_act2);
    cudaGetSymbolAddress((void**)&whi0, g_whi0);
    cudaGetSymbolAddress((void**)&wlo0, g_wlo0);
    cudaGetSymbolAddress((void**)&whi1, g_whi1);
    cudaGetSymbolAddress((void**)&wlo1, g_wlo1);
    cudaGetSymbolAddress((void**)&whi2, g_whi2);
    cudaGetSymbolAddress((void**)&wlo2, g_wlo2);
    cudaGetSymbolAddress((void**)&msum, g_msum);
    cudaGetSymbolAddress((void**)&cb,   g_cb);

    cudaFuncSetAttribute(fused_layer_kernel<128, false>,
                         cudaFuncAttributeMaxDynamicSharedMemorySize, SMEM_BYTES);
    cudaFuncSetAttribute(fused_layer_kernel<256, false>,
                         cudaFuncAttributeMaxDynamicSharedMemorySize, SMEM_BYTES);
    cudaFuncSetAttribute(fused_layer_kernel<256, true>,
                         cudaFuncAttributeMaxDynamicSharedMemorySize, SMEM_BYTES);

    dim3 gg(M_ROWS / 128, 2);

    // prep: weights (hi/lo fp16) + x fp16 plane (in g_act2)
    prep_w_kernel<<<H_DIM, 256>>>(W0, 256, 128, whi0, wlo0);
    prep_w_kernel<<<H_DIM, 256>>>(W1, 512, 256, whi1, wlo1);
    prep_w_kernel<<<H_DIM, 256>>>(W2, 512, 256, whi2, wlo2);
    prep_x_kernel<<<(M_ROWS * 128) / 2048, 256>>>(x, act2);

    // Layer 0
    zero_kernel<<<B_SETS, 256>>>(msum, B_SETS * H_DIM);
    mean_sum_x_kernel<<<dim3(B_SETS, 8), 128>>>(x, msum);
    cbias_kernel<<<B_SETS, H_DIM>>>(msum, W0, b0, cb, 128, 256, 128);
    zero_kernel<<<B_SETS, 256>>>(msum, B_SETS * H_DIM);
    fused_layer_kernel<128, false><<<gg, 256, SMEM_BYTES>>>(
        act2, whi0, wlo0, cb, act1, msum);

    // Layer 1 (reads act1, writes act2 — x plane no longer needed)
    cbias_kernel<<<B_SETS, H_DIM>>>(msum, W1, b1, cb, 256, 512, 256);
    zero_kernel<<<B_SETS, 256>>>(msum, B_SETS * H_DIM);
    fused_layer_kernel<256, false><<<gg, 256, SMEM_BYTES>>>(
        act1, whi1, wlo1, cb, act2, msum);

    // Layer 2 (final)
    cbias_kernel<<<B_SETS, H_DIM>>>(msum, W2, b2, cb, 256, 512, 256);
    zero_kernel<<<B_SETS, 256>>>(out, B_SETS * H_DIM);
    fused_layer_kernel<256, true><<<gg, 256, SMEM_BYTES>>>(
        act2, whi2, wlo2, cb, nullptr, out);
}

// round 11
// speedup vs baseline: 4.7276x; 1.3469x over previous
#include <cuda_runtime.h>
#include <cuda_fp16.h>
#include <cstdint>

#define B_SETS 256
#define S_LEN  1024
#define H_DIM  256
#define M_ROWS (B_SETS * S_LEN)

// ---------------------------------------------------------------------------
// Scratch (__device__ globals; allocation-free rule)
// ---------------------------------------------------------------------------
__device__ __half g_act1[(size_t)M_ROWS * H_DIM];  // 128 MB
__device__ __half g_act2[(size_t)M_ROWS * H_DIM];  // 128 MB (x plane for L0)
__device__ __half g_w0[H_DIM * 128];
__device__ __half g_w1[H_DIM * H_DIM];
__device__ __half g_w2[H_DIM * H_DIM];
__device__ float g_msum[B_SETS * H_DIM];   // column sums (per set)
__device__ float g_cb[B_SETS * H_DIM];     // per-set bias c[b,h]

// ---------------------------------------------------------------------------
// helpers
// ---------------------------------------------------------------------------
__device__ __forceinline__ uint32_t smem_u32(const void* p) {
    uint32_t a;
    asm("{ .reg .u64 t; cvta.to.shared.u64 t, %1; cvt.u32.u64 %0, t; }" : "=r"(a) : "l"(p));
    return a;
}
#define SW128(o) ((uint32_t)(o) ^ ((((uint32_t)(o)) >> 3) & 0x70u))

__device__ __forceinline__ void ldsm_x4(uint32_t* r, uint32_t addr) {
    asm volatile("ldmatrix.sync.aligned.m8n8.x4.shared.b16 {%0,%1,%2,%3}, [%4];"
                 : "=r"(r[0]), "=r"(r[1]), "=r"(r[2]), "=r"(r[3]) : "r"(addr));
}
__device__ __forceinline__ void mma_fp16(float* d, const uint32_t* a, uint32_t b0, uint32_t b1) {
    asm volatile(
        "mma.sync.aligned.m16n8k16.row.col.f32.f16.f16.f32 "
        "{%0,%1,%2,%3},{%4,%5,%6,%7},{%8,%9},{%0,%1,%2,%3};"
        : "+f"(d[0]), "+f"(d[1]), "+f"(d[2]), "+f"(d[3])
        : "r"(a[0]), "r"(a[1]), "r"(a[2]), "r"(a[3]), "r"(b0), "r"(b1));
}
__device__ __forceinline__ float tanh_fast(float x) {
    float r;
    asm("tanh.approx.f32 %0, %1;" : "=f"(r) : "f"(x));
    return r;
}
__device__ __forceinline__ uint32_t pack2h(float a, float b) {
    __half2 t = __floats2half2_rn(a, b);
    return *reinterpret_cast<uint32_t*>(&t);
}
__device__ __forceinline__ void cpa16(uint32_t dst, const void* src) {
    asm volatile("cp.async.cg.shared.global [%0], [%1], 16;" :: "r"(dst), "l"(src));
}
__device__ __forceinline__ void cpa_commit() {
    asm volatile("cp.async.commit_group;");
}
template<int N>
__device__ __forceinline__ void cpa_wait() {
    asm volatile("cp.async.wait_group %0;" :: "n"(N));
}

// ---------------------------------------------------------------------------
// small kernels
// ---------------------------------------------------------------------------
__global__ void prep_w_kernel(const float* __restrict__ W, int ldw, int K,
                              __half* __restrict__ hi) {
    int n = blockIdx.x;
    for (int k = threadIdx.x; k < K; k += blockDim.x)
        hi[n * K + k] = __float2half_rn(W[(size_t)n * ldw + k]);
}

// x fp32 -> single fp16 plane (vectorized, 8 elems/thread)
__global__ void prep_x_kernel(const float* __restrict__ x, __half* __restrict__ hi) {
    size_t i = ((size_t)blockIdx.x * 256 + threadIdx.x) * 8;
    float4 v0 = *(const float4*)(x + i);
    float4 v1 = *(const float4*)(x + i + 4);
    uint4 h;
    h.x = pack2h(v0.x, v0.y);
    h.y = pack2h(v0.z, v0.w);
    h.z = pack2h(v1.x, v1.y);
    h.w = pack2h(v1.z, v1.w);
    *(uint4*)(hi + i) = h;
}

// partial mean: grid (B_SETS, 8), block 128 — atomicAdd into msum (pre-zeroed)
__global__ void mean_sum_x_kernel(const float* __restrict__ x, float* __restrict__ out) {
    int b = blockIdx.x, cz = blockIdx.y, t = threadIdx.x;
    const float* p = x + (size_t)b * S_LEN * 128 + (size_t)cz * 128 * 128 + t;
    float s = 0.f;
#pragma unroll 8
    for (int i = 0; i < 128; i++) s += p[(size_t)i * 128];
    atomicAdd(out + b * 128 + t, s);
}

__global__ void cbias_kernel(const float* __restrict__ msum, const float* __restrict__ W,
                             const float* __restrict__ bias, float* __restrict__ c,
                             int K, int ldw, int koff) {
    __shared__ float ms[H_DIM];
    int b = blockIdx.x, h = threadIdx.x;
    if (h < K) ms[h] = msum[b * K + h] * (1.0f / S_LEN);
    __syncthreads();
    const float* wr = W + (size_t)h * ldw + koff;
    float s = bias[h];
#pragma unroll 8
    for (int k = 0; k < K; k++) s += ms[k] * wr[k];
    c[b * H_DIM + h] = s;
}

__global__ void zero_kernel(float* p, int n) {
    int i = blockIdx.x * 256 + threadIdx.x;
    if (i < n) p[i] = 0.f;
}

// ---------------------------------------------------------------------------
// Fused layer (fp16 HMMA, cp.async 3-stage pipeline, single-term):
// CTA: Out[128 x 128] = tanh(A[128xK] W[128xK]^T + cbias)
// A, W single fp16 planes. K chunk 64 (128B rows, SW128).
// 8 warps: 4 in M x 2 in N. Writes fp16 activations, accumulates column sums.
// ---------------------------------------------------------------------------
#define A_PL 0
#define W_PL 16384
#define STAGE_BYTES 32768
#define NSTAGE 3
#define SMEM_BYTES  (NSTAGE * STAGE_BYTES)

template<int K_TOTAL, bool FINAL>
__global__ __launch_bounds__(256, 2) void fused_layer_kernel(
    const __half* __restrict__ A,
    const __half* __restrict__ W,
    const float* __restrict__ Cb,
    __half* __restrict__ Oact,
    float* __restrict__ Osum)
{
    extern __shared__ char smem_raw[];
    char* tb = smem_raw;
    const uint32_t sb = smem_u32(tb);

    const int tid  = threadIdx.x;
    const int wid  = tid >> 5;
    const int lane = tid & 31;
    const int warp_m = wid & 3;
    const int warp_n = wid >> 2;
    const int m0 = blockIdx.x * 128;
    const int n0 = blockIdx.y * 128;
    const int set = m0 >> 10;

    float acc[2][8][4];
#pragma unroll
    for (int a = 0; a < 2; a++)
#pragma unroll
        for (int b = 0; b < 8; b++)
#pragma unroll
            for (int c = 0; c < 4; c++) acc[a][b][c] = 0.f;

    const int NCHUNK = K_TOTAL / 64;

    // per plane: 128 rows x 128B = 1024 x 16B units; 256 threads -> 4 units each
    auto issue_chunk = [&](int ch, int st) {
        const uint32_t sbase = sb + st * STAGE_BYTES;
#pragma unroll
        for (int i = 0; i < 4; i++) {
            int u = i * 256 + tid;
            int row = u >> 3, c16 = u & 7;
            uint32_t doff = SW128(row * 128 + c16 * 16);
            size_t asrc = (size_t)(m0 + row) * K_TOTAL + ch * 64 + c16 * 8;
            size_t wsrc = (size_t)(n0 + row) * K_TOTAL + ch * 64 + c16 * 8;
            cpa16(sbase + A_PL + doff, A + asrc);
            cpa16(sbase + W_PL + doff, W + wsrc);
        }
        cpa_commit();
    };

    issue_chunk(0, 0);
    if (NCHUNK > 1) issue_chunk(1, 1);

    const int r16 = lane & 15;
    const int kb  = (lane >> 4) * 16;

    for (int ch = 0; ch < NCHUNK; ch++) {
        const int st = ch % NSTAGE;
        if (ch + 2 < NCHUNK) {
            issue_chunk(ch + 2, (ch + 2) % NSTAGE);
            cpa_wait<2>();
        } else if (ch + 1 < NCHUNK) {
            cpa_wait<1>();
        } else {
            cpa_wait<0>();
        }
        __syncthreads();

        const uint32_t sbase = sb + st * STAGE_BYTES;
#pragma unroll
        for (int kk = 0; kk < 4; kk++) {
            const uint32_t colb = (uint32_t)(kk * 32 + kb);
            uint32_t ah[2][4];
#pragma unroll
            for (int mt = 0; mt < 2; mt++) {
                uint32_t off = SW128((warp_m * 32 + mt * 16 + r16) * 128 + colb);
                ldsm_x4(ah[mt], sbase + A_PL + off);
            }
#pragma unroll
            for (int p = 0; p < 4; p++) {
                uint32_t offB = SW128((warp_n * 64 + p * 16 + r16) * 128 + colb);
                uint32_t bh[4];
                ldsm_x4(bh, sbase + W_PL + offB);
#pragma unroll
                for (int mt = 0; mt < 2; mt++) {
                    mma_fp16(acc[mt][2 * p],     ah[mt], bh[0], bh[2]);
                    mma_fp16(acc[mt][2 * p + 1], ah[mt], bh[1], bh[3]);
                }
            }
        }
        __syncthreads();
    }

    // ---- epilogue ----
    float* cbs = (float*)tb;
    if (tid < 128) cbs[tid] = Cb[set * 256 + n0 + tid];
    __syncthreads();

    const int lq = lane >> 2;
    const int lr = lane & 3;

    float colsum[8][2];
#pragma unroll
    for (int nt = 0; nt < 8; nt++) { colsum[nt][0] = 0.f; colsum[nt][1] = 0.f; }

#pragma unroll
    for (int mt = 0; mt < 2; mt++) {
        const int rbase = m0 + warp_m * 32 + mt * 16 + lq;
#pragma unroll
        for (int nt = 0; nt < 8; nt++) {
            const int lc = warp_n * 64 + nt * 8 + 2 * lr;
            float v0 = tanh_fast(acc[mt][nt][0] + cbs[lc]);
            float v1 = tanh_fast(acc[mt][nt][1] + cbs[lc + 1]);
            float v2 = tanh_fast(acc[mt][nt][2] + cbs[lc]);
            float v3 = tanh_fast(acc[mt][nt][3] + cbs[lc + 1]);
            colsum[nt][0] += v0 + v2;
            colsum[nt][1] += v1 + v3;
            if (!FINAL) {
                *(uint32_t*)(Oact + (size_t)rbase * 256 + n0 + lc)       = pack2h(v0, v1);
                *(uint32_t*)(Oact + (size_t)(rbase + 8) * 256 + n0 + lc) = pack2h(v2, v3);
            }
        }
    }
#pragma unroll
    for (int nt = 0; nt < 8; nt++) {
#pragma unroll
        for (int h = 0; h < 2; h++) {
            float s = colsum[nt][h];
            s += __shfl_xor_sync(0xffffffffu, s, 4);
            s += __shfl_xor_sync(0xffffffffu, s, 8);
            s += __shfl_xor_sync(0xffffffffu, s, 16);
            if (lq == 0) {
                int gc = n0 + warp_n * 64 + nt * 8 + 2 * lr + h;
                atomicAdd(Osum + set * 256 + gc, FINAL ? s * (1.0f / S_LEN) : s);
            }
        }
    }
}

// ---------------------------------------------------------------------------
extern "C" void kernel_launch(void* const* d_in, const int* in_sizes, int n_in,
                              void* d_out, int out_size) {
    const float* x  = (const float*)d_in[0];
    const float* W0 = (const float*)d_in[1];
    const float* b0 = (const float*)d_in[2];
    const float* W1 = (const float*)d_in[3];
    const float* b1 = (const float*)d_in[4];
    const float* W2 = (const float*)d_in[5];
    const float* b2 = (const float*)d_in[6];
    float* out = (float*)d_out;

    __half *act1, *act2, *w0, *w1, *w2;
    float *msum, *cb;
    cudaGetSymbolAddress((void**)&act1, g_act1);
    cudaGetSymbolAddress((void**)&act2, g_act2);
    cudaGetSymbolAddress((void**)&w0, g_w0);
    cudaGetSymbolAddress((void**)&w1, g_w1);
    cudaGetSymbolAddress((void**)&w2, g_w2);
    cudaGetSymbolAddress((void**)&msum, g_msum);
    cudaGetSymbolAddress((void**)&cb,   g_cb);

    cudaFuncSetAttribute(fused_layer_kernel<128, false>,
                         cudaFuncAttributeMaxDynamicSharedMemorySize, SMEM_BYTES);
    cudaFuncSetAttribute(fused_layer_kernel<256, false>,
                         cudaFuncAttributeMaxDynamicSharedMemorySize, SMEM_BYTES);
    cudaFuncSetAttribute(fused_layer_kernel<256, true>,
                         cudaFuncAttributeMaxDynamicSharedMemorySize, SMEM_BYTES);

    dim3 gg(M_ROWS / 128, 2);

    // prep: weights (fp16) + x fp16 plane (in g_act2)
    prep_w_kernel<<<H_DIM, 256>>>(W0, 256, 128, w0);
    prep_w_kernel<<<H_DIM, 256>>>(W1, 512, 256, w1);
    prep_w_kernel<<<H_DIM, 256>>>(W2, 512, 256, w2);
    prep_x_kernel<<<(M_ROWS * 128) / 2048, 256>>>(x, act2);

    // Layer 0
    zero_kernel<<<B_SETS, 256>>>(msum, B_SETS * H_DIM);
    mean_sum_x_kernel<<<dim3(B_SETS, 8), 128>>>(x, msum);
    cbias_kernel<<<B_SETS, H_DIM>>>(msum, W0, b0, cb, 128, 256, 128);
    zero_kernel<<<B_SETS, 256>>>(msum, B_SETS * H_DIM);
    fused_layer_kernel<128, false><<<gg, 256, SMEM_BYTES>>>(
        act2, w0, cb, act1, msum);

    // Layer 1 (reads act1, writes act2 — x plane no longer needed)
    cbias_kernel<<<B_SETS, H_DIM>>>(msum, W1, b1, cb, 256, 512, 256);
    zero_kernel<<<B_SETS, 256>>>(msum, B_SETS * H_DIM);
    fused_layer_kernel<256, false><<<gg, 256, SMEM_BYTES>>>(
        act1, w1, cb, act2, msum);

    // Layer 2 (final)
    cbias_kernel<<<B_SETS, H_DIM>>>(msum, W2, b2, cb, 256, 512, 256);
    zero_kernel<<<B_SETS, 256>>>(out, B_SETS * H_DIM);
    fused_layer_kernel<256, true><<<gg, 256, SMEM_BYTES>>>(
        act2, w2, cb, nullptr, out);
}